// round 15
// baseline (speedup 1.0000x reference)
#include <cuda_runtime.h>
#include <cuda_fp16.h>
#include <stdint.h>

#define ED   1024
#define NH   16
#define HD   64
#define SEQ  2048
#define BATCH 2
#define MTOT (BATCH*SEQ)

// scratch (__device__ globals: allocation-free rule)
__device__ __half g_Qh[MTOT * ED];
__device__ __half g_Kh[MTOT * ED];
__device__ __half g_Vh[MTOT * ED];
__device__ __half g_xh[MTOT * ED];
__device__ __half g_ch[MTOT * ED];
__device__ __half g_wh[4][ED * ED];        // K-major [N][K]; [0..2] packed QKV

// Q pre-scale: (1/sqrt(64)) * log2(e)  -> softmax in exp2 domain
#define QSCALE 0.1803368801111164f

// ---------------------------------------------------------------------------
// helpers
// ---------------------------------------------------------------------------
__device__ __forceinline__ uint32_t packh(__half a, __half b) {
    return (uint32_t)__half_as_ushort(a) | ((uint32_t)__half_as_ushort(b) << 16);
}
__device__ __forceinline__ void mma16(float* d, const uint32_t* a, uint32_t b0, uint32_t b1) {
    asm volatile(
        "mma.sync.aligned.m16n8k16.row.col.f32.f16.f16.f32 "
        "{%0,%1,%2,%3}, {%4,%5,%6,%7}, {%8,%9}, {%0,%1,%2,%3};\n"
        : "+f"(d[0]), "+f"(d[1]), "+f"(d[2]), "+f"(d[3])
        : "r"(a[0]), "r"(a[1]), "r"(a[2]), "r"(a[3]), "r"(b0), "r"(b1));
}
__device__ __forceinline__ void cpa16(void* sdst, const void* gsrc) {
    uint32_t sa = (uint32_t)__cvta_generic_to_shared(sdst);
    asm volatile("cp.async.cg.shared.global [%0], [%1], 16;\n" :: "r"(sa), "l"(gsrc));
}
#define CP_COMMIT() asm volatile("cp.async.commit_group;\n" ::: "memory")
#define CP_WAIT1()  asm volatile("cp.async.wait_group 1;\n" ::: "memory")
#define CP_WAIT0()  asm volatile("cp.async.wait_group 0;\n" ::: "memory")

__device__ __forceinline__ void ldmx4(uint32_t& r0, uint32_t& r1, uint32_t& r2,
                                      uint32_t& r3, uint32_t saddr) {
    asm volatile("ldmatrix.sync.aligned.m8n8.x4.shared.b16 {%0,%1,%2,%3}, [%4];"
                 : "=r"(r0), "=r"(r1), "=r"(r2), "=r"(r3) : "r"(saddr));
}
__device__ __forceinline__ void ldmx4t(uint32_t& r0, uint32_t& r1, uint32_t& r2,
                                       uint32_t& r3, uint32_t saddr) {
    asm volatile("ldmatrix.sync.aligned.m8n8.x4.trans.shared.b16 {%0,%1,%2,%3}, [%4];"
                 : "=r"(r0), "=r"(r1), "=r"(r2), "=r"(r3) : "r"(saddr));
}
__device__ __forceinline__ void ldmx2t(uint32_t& r0, uint32_t& r1, uint32_t saddr) {
    asm volatile("ldmatrix.sync.aligned.m8n8.x2.trans.shared.b16 {%0,%1}, [%2];"
                 : "=r"(r0), "=r"(r1) : "r"(saddr));
}

// ---------------------------------------------------------------------------
// rounding kernels (fp32 -> fp16 RNE)
// ---------------------------------------------------------------------------
__global__ void __launch_bounds__(256)
around(const float* __restrict__ A, __half* __restrict__ oh)
{
    int i = blockIdx.x * 256 + threadIdx.x;
    float4 v = ((const float4*)A)[i];
    ((uint2*)oh)[i] = make_uint2(packh(__float2half_rn(v.x), __float2half_rn(v.y)),
                                 packh(__float2half_rn(v.z), __float2half_rn(v.w)));
}
__global__ void __launch_bounds__(256)
wround4(const float* __restrict__ W0, const float* __restrict__ W1,
        const float* __restrict__ W2, const float* __restrict__ W3,
        __half* __restrict__ bhBase)
{
    __shared__ float t[32][33];
    const float* W = (blockIdx.z == 0) ? W0 : (blockIdx.z == 1) ? W1
                   : (blockIdx.z == 2) ? W2 : W3;
    __half* bh = bhBase + (size_t)blockIdx.z * ED * ED;
    int k0 = blockIdx.x * 32, n0 = blockIdx.y * 32;
    int tx = threadIdx.x, ty = threadIdx.y;            // (32, 8)
    #pragma unroll
    for (int i = 0; i < 4; i++)
        t[ty + 8 * i][tx] = W[(size_t)(k0 + ty + 8 * i) * ED + n0 + tx];
    __syncthreads();
    #pragma unroll
    for (int i = 0; i < 4; i++)
        bh[(size_t)(n0 + ty + 8 * i) * ED + k0 + tx] = __float2half_rn(t[tx][ty + 8 * i]);
}

// ---------------------------------------------------------------------------
// fp16 GEMM: 128x128 tile, k-chunk 64, 8 warps (2x4), warp tile 64x32.
// 3-stage cp.async ring (prefetch depth 2, dynamic smem 108KB), ONE barrier
// per chunk. ldmatrix.x4 frag loads. Pitch 72.
// ---------------------------------------------------------------------------
#define GP   72
#define GSTG (128 * GP)                 // halves per array (A or B) per stage
#define GST2 (2 * GSTG)                 // halves per ring stage (A + B)
#define NCH  16                         // k chunks of 64
#define GEMM_SMEM (3 * GST2 * 2)        // 110592 bytes

#define GEMM_MAIN(A_, B_)                                                          \
    extern __shared__ __half hsm[];                                                \
    const int tid = threadIdx.x;                                                   \
    const int w = tid >> 5, lane = tid & 31, g = lane >> 2, t = lane & 3;          \
    const int wm = w >> 2, wn = w & 3;                                             \
    const int m0 = blockIdx.y * 128;                                               \
    const int nrow0 = blockIdx.x * 128;                                            \
    const uint32_t hsmu = (uint32_t)__cvta_generic_to_shared(hsm);                 \
    const uint32_t aoff = (uint32_t)(((lane & 15) * GP + (lane >> 4) * 8) * 2);    \
    const uint32_t boff = (uint32_t)((((lane & 7) + ((lane >> 4) << 3)) * GP +     \
                                      (((lane >> 3) & 1) * 8)) * 2);               \
    float acc[4][4][4] = {};                                                       \
    auto stage = [&](int c, int s) {                                               \
        __half* base = hsm + (size_t)s * GST2;                                     \
        const int k0 = c * 64;                                                     \
        _Pragma("unroll")                                                          \
        for (int i = 0; i < 4; i++) {                                              \
            int id = i * 256 + tid;                                                \
            int r = id >> 3, c8 = (id & 7) << 3;                                   \
            cpa16(base + r * GP + c8,        A_ + (size_t)(m0 + r) * ED + k0 + c8);\
            cpa16(base + GSTG + r * GP + c8, B_ + (size_t)(nrow0 + r) * ED + k0 + c8);\
        }                                                                          \
        CP_COMMIT();                                                               \
    };                                                                             \
    stage(0, 0);                                                                   \
    stage(1, 1);                                                                   \
    for (int c = 0; c < NCH; c++) {                                                \
        if (c < NCH - 1) { CP_WAIT1(); } else { CP_WAIT0(); }                      \
        __syncthreads();  /* chunk c visible; slot (c+2)%3's readers done */       \
        if (c + 2 < NCH) stage(c + 2, (c + 2) % 3);                                \
        const uint32_t cAu = hsmu + (uint32_t)((c % 3) * GST2 * 2);                \
        const uint32_t cBu = cAu + (uint32_t)(GSTG * 2);                           \
        _Pragma("unroll")                                                          \
        for (int ks = 0; ks < 4; ks++) {                                           \
            uint32_t af[4][4];                                                     \
            _Pragma("unroll")                                                      \
            for (int mt = 0; mt < 4; mt++)                                         \
                ldmx4(af[mt][0], af[mt][1], af[mt][2], af[mt][3],                  \
                      cAu + (uint32_t)((((wm * 64 + mt * 16) * GP) + ks * 16) * 2) \
                          + aoff);                                                 \
            uint32_t bf[4][2];                                                     \
            _Pragma("unroll")                                                      \
            for (int np = 0; np < 2; np++)                                         \
                ldmx4(bf[2 * np][0], bf[2 * np][1], bf[2 * np + 1][0],             \
                      bf[2 * np + 1][1],                                           \
                      cBu + (uint32_t)((((wn * 32 + np * 16) * GP) + ks * 16) * 2) \
                          + boff);                                                 \
            _Pragma("unroll")                                                      \
            for (int mt = 0; mt < 4; mt++)                                         \
                _Pragma("unroll")                                                  \
                for (int nc = 0; nc < 4; nc++)                                     \
                    mma16(acc[mt][nc], af[mt], bf[nc][0], bf[nc][1]);              \
        }                                                                          \
    }

// fused QKV: B packed [3072][1024]; seg 0=Q (xQSCALE, exp2 domain), 1=K, 2=V
__global__ void __launch_bounds__(256, 2)
gemm_qkv(const __half* __restrict__ A, const __half* __restrict__ B,
         const float* __restrict__ bq, const float* __restrict__ bk,
         const float* __restrict__ bv,
         __half* __restrict__ Qh, __half* __restrict__ Kh, __half* __restrict__ Vh)
{
    GEMM_MAIN(A, B)

    const int seg = blockIdx.x >> 3;
    const int ncol0 = (blockIdx.x & 7) * 128;
    const float* bias = (seg == 0) ? bq : (seg == 1) ? bk : bv;
    __half* O = (seg == 0) ? Qh : (seg == 1) ? Kh : Vh;
    const float sc = (seg == 0) ? QSCALE : 1.0f;

    #pragma unroll
    for (int mt = 0; mt < 4; mt++) {
        int row = m0 + wm * 64 + mt * 16 + g;
        #pragma unroll
        for (int nc = 0; nc < 4; nc++) {
            int col = ncol0 + wn * 32 + nc * 8 + 2 * t;
            float b0 = bias[col], b1 = bias[col + 1];
            *(uint32_t*)(O + (size_t)row * ED + col) =
                packh(__float2half_rn((acc[mt][nc][0] + b0) * sc),
                      __float2half_rn((acc[mt][nc][1] + b1) * sc));
            *(uint32_t*)(O + (size_t)(row + 8) * ED + col) =
                packh(__float2half_rn((acc[mt][nc][2] + b0) * sc),
                      __float2half_rn((acc[mt][nc][3] + b1) * sc));
        }
    }
}

// O projection: float out
__global__ void __launch_bounds__(256, 2)
gemm_o(const __half* __restrict__ A, const __half* __restrict__ B,
       const float* __restrict__ bias, float* __restrict__ out)
{
    GEMM_MAIN(A, B)

    #pragma unroll
    for (int mt = 0; mt < 4; mt++) {
        int row = m0 + wm * 64 + mt * 16 + g;
        #pragma unroll
        for (int nc = 0; nc < 4; nc++) {
            int col = nrow0 + wn * 32 + nc * 8 + 2 * t;
            float b0 = bias[col], b1 = bias[col + 1];
            *(float2*)(out + (size_t)row * ED + col) =
                make_float2(acc[mt][nc][0] + b0, acc[mt][nc][1] + b1);
            *(float2*)(out + (size_t)(row + 8) * ED + col) =
                make_float2(acc[mt][nc][2] + b0, acc[mt][nc][3] + b1);
        }
    }
}

// ---------------------------------------------------------------------------
// fp16 flash attention (exact R11 structure), exp2 domain, 2 CTAs/SM.
// h2exp2 P; row-sum via ones-block mma (V cols 64..71, all ones).
// ---------------------------------------------------------------------------
#define PH   72
#define HSTG (64 * PH)

__global__ void __launch_bounds__(256, 2)
attn_h(const __half* __restrict__ Q, const __half* __restrict__ K,
       const __half* __restrict__ V, const float* __restrict__ X,
       __half* __restrict__ CH)
{
    __shared__ __half asm_[4 * HSTG];       // 36864 B
    __half* sK = asm_;
    __half* sV = asm_ + 2 * HSTG;

    const int tid = threadIdx.x;
    const int w = tid >> 5, lane = tid & 31, g = lane >> 2, t = lane & 3;
    const int qt = blockIdx.x, h = blockIdx.y, b = blockIdx.z;
    const int qrow0 = b * SEQ + qt * 128;
    const int coff  = h * HD;

    const int matq = lane >> 3;
    const uint32_t ldmoffV = (uint32_t)((((matq & 1) * 8 + (lane & 7)) * PH +
                                         (matq >> 1) * 8) * 2);          // V x4 trans
    const uint32_t ldmoffK = (uint32_t)((((lane & 7) + ((lane >> 4) << 3)) * PH +
                                         (((lane >> 3) & 1) * 8)) * 2);  // K x4 B-frag
    const uint32_t ldmoffL = (uint32_t)(((((lane >> 3) & 1) * 8 + (lane & 7)) * PH) * 2)
                             + 64 * 2;                                   // ones x2 trans
    const uint32_t sKu = (uint32_t)__cvta_generic_to_shared(sK);
    const uint32_t sVu = (uint32_t)__cvta_generic_to_shared(sV);

    // init V cols 64..71 in both buffers: ALL ones (row-sum via mma, lane-uniform)
    for (int i = tid; i < 2 * 64; i += 256) {
        int bf = i >> 6, r = i & 63;
        __half* dst = sV + bf * HSTG + r * PH + 64;
        #pragma unroll
        for (int j = 0; j < 8; j++) dst[j] = __float2half(1.0f);
    }

    uint32_t qf[4][4];
    {
        const int r0 = qrow0 + w * 16 + g;
        #pragma unroll
        for (int kc = 0; kc < 4; kc++) {
            int c0 = coff + kc * 16 + 2 * t;
            qf[kc][0] = *(const uint32_t*)(Q + (size_t)r0 * ED + c0);
            qf[kc][1] = *(const uint32_t*)(Q + (size_t)(r0 + 8) * ED + c0);
            qf[kc][2] = *(const uint32_t*)(Q + (size_t)r0 * ED + c0 + 8);
            qf[kc][3] = *(const uint32_t*)(Q + (size_t)(r0 + 8) * ED + c0 + 8);
        }
    }

    auto stage = [&](int kt, int s) {
        const int krow0 = b * SEQ + kt * 64;
        __half* dK = sK + s * HSTG;
        __half* dV = sV + s * HSTG;
        #pragma unroll
        for (int i = 0; i < 2; i++) {
            int id = i * 256 + tid;
            int r = id >> 3, c8 = (id & 7) << 3;
            cpa16(dK + r * PH + c8, K + (size_t)(krow0 + r) * ED + coff + c8);
            cpa16(dV + r * PH + c8, V + (size_t)(krow0 + r) * ED + coff + c8);
        }
        CP_COMMIT();
    };

    stage(0, 0);

    float m1 = -1e30f, m2 = -1e30f;
    float ol[4] = {};                        // [0]=l(row g), [2]=l(row g+8)
    float o[8][4] = {};

    int buf = 0;
    for (int kt = 0; kt < SEQ / 64; kt++) {
        if (kt + 1 < SEQ / 64) { stage(kt + 1, buf ^ 1); CP_WAIT1(); }
        else                   { CP_WAIT0(); }
        __syncthreads();

        const uint32_t cKu = sKu + (uint32_t)(buf * HSTG * 2);
        const uint32_t cVu = sVu + (uint32_t)(buf * HSTG * 2);

        // S = Q @ K^T
        float s[8][4] = {};
        #pragma unroll
        for (int kc = 0; kc < 4; kc++) {
            #pragma unroll
            for (int np = 0; np < 4; np++) {
                uint32_t b00, b01, b10, b11;
                ldmx4(b00, b01, b10, b11,
                      cKu + (uint32_t)((np * 16 * PH + kc * 16) * 2) + ldmoffK);
                mma16(s[2 * np],     qf[kc], b00, b01);
                mma16(s[2 * np + 1], qf[kc], b10, b11);
            }
        }

        // online softmax in exp2 domain (rows g, g+8; quad reduce for max)
        float tm1 = -1e30f, tm2 = -1e30f;
        #pragma unroll
        for (int nc = 0; nc < 8; nc++) {
            tm1 = fmaxf(tm1, fmaxf(s[nc][0], s[nc][1]));
            tm2 = fmaxf(tm2, fmaxf(s[nc][2], s[nc][3]));
        }
        tm1 = fmaxf(tm1, __shfl_xor_sync(0xffffffffu, tm1, 1));
        tm1 = fmaxf(tm1, __shfl_xor_sync(0xffffffffu, tm1, 2));
        tm2 = fmaxf(tm2, __shfl_xor_sync(0xffffffffu, tm2, 1));
        tm2 = fmaxf(tm2, __shfl_xor_sync(0xffffffffu, tm2, 2));

        float mn1 = fmaxf(m1, tm1), mn2 = fmaxf(m2, tm2);
        float c1 = exp2f(m1 - mn1), c2 = exp2f(m2 - mn2);
        m1 = mn1; m2 = mn2;

        // P in fp16 via packed MUFU exp2
        uint32_t p0[8], p1[8];
        #pragma unroll
        for (int nc = 0; nc < 8; nc++) {
            __half2 e01 = h2exp2(__floats2half2_rn(s[nc][0] - mn1, s[nc][1] - mn1));
            __half2 e23 = h2exp2(__floats2half2_rn(s[nc][2] - mn2, s[nc][3] - mn2));
            p0[nc] = *(uint32_t*)&e01;
            p1[nc] = *(uint32_t*)&e23;
        }

        // rescale running O and l
        ol[0] *= c1; ol[2] *= c2;
        #pragma unroll
        for (int nc = 0; nc < 8; nc++) {
            o[nc][0] *= c1; o[nc][1] *= c1;
            o[nc][2] *= c2; o[nc][3] *= c2;
        }

        // O += P @ V ; l += P @ ones (V ones-block)
        #pragma unroll
        for (int kc = 0; kc < 4; kc++) {
            uint32_t a[4] = { p0[2 * kc], p1[2 * kc], p0[2 * kc + 1], p1[2 * kc + 1] };
            uint32_t lb0, lb1;
            ldmx2t(lb0, lb1, cVu + (uint32_t)((kc * 16 * PH) * 2) + ldmoffL);
            mma16(ol, a, lb0, lb1);
            #pragma unroll
            for (int np = 0; np < 4; np++) {
                uint32_t r0, r1, r2, r3;
                ldmx4t(r0, r1, r2, r3,
                       cVu + (uint32_t)((kc * 16 * PH + np * 16) * 2) + ldmoffV);
                mma16(o[2 * np],     a, r0, r1);
                mma16(o[2 * np + 1], a, r2, r3);
            }
        }

        __syncthreads();
        buf ^= 1;
    }

    const float i1 = 1.f / ol[0], i2 = 1.f / ol[2];
    const int r0 = qrow0 + w * 16 + g;
    #pragma unroll
    for (int nc = 0; nc < 8; nc++) {
        int col = coff + nc * 8 + 2 * t;
        float2 x0 = *(const float2*)(X + (size_t)r0 * ED + col);
        float2 x1 = *(const float2*)(X + (size_t)(r0 + 8) * ED + col);
        *(uint32_t*)(CH + (size_t)r0 * ED + col) =
            packh(__float2half_rn(o[nc][0] * i1 + x0.x),
                  __float2half_rn(o[nc][1] * i1 + x0.y));
        *(uint32_t*)(CH + (size_t)(r0 + 8) * ED + col) =
            packh(__float2half_rn(o[nc][2] * i2 + x1.x),
                  __float2half_rn(o[nc][3] * i2 + x1.y));
    }
}

// ---------------------------------------------------------------------------
extern "C" void kernel_launch(void* const* d_in, const int* in_sizes, int n_in,
                              void* d_out, int out_size)
{
    const float* x  = (const float*)d_in[0];
    const float* wq = (const float*)d_in[1];
    const float* bq = (const float*)d_in[2];
    const float* wk = (const float*)d_in[3];
    const float* bk = (const float*)d_in[4];
    const float* wv = (const float*)d_in[5];
    const float* bv = (const float*)d_in[6];
    const float* wo = (const float*)d_in[7];
    const float* bo = (const float*)d_in[8];
    float* out = (float*)d_out;

    __half *Qh, *Kh, *Vh, *xh, *ch, *wh;
    cudaGetSymbolAddress((void**)&Qh, g_Qh);
    cudaGetSymbolAddress((void**)&Kh, g_Kh);
    cudaGetSymbolAddress((void**)&Vh, g_Vh);
    cudaGetSymbolAddress((void**)&xh, g_xh);
    cudaGetSymbolAddress((void**)&ch, g_ch);
    cudaGetSymbolAddress((void**)&wh, g_wh);

    cudaFuncSetAttribute(gemm_qkv, cudaFuncAttributeMaxDynamicSharedMemorySize, GEMM_SMEM);
    cudaFuncSetAttribute(gemm_o,   cudaFuncAttributeMaxDynamicSharedMemorySize, GEMM_SMEM);

    around<<<MTOT * ED / 1024, 256>>>(x, xh);
    wround4<<<dim3(ED / 32, ED / 32, 4), dim3(32, 8)>>>(wq, wk, wv, wo, wh);

    gemm_qkv<<<dim3(3 * ED / 128, MTOT / 128), 256, GEMM_SMEM>>>(xh, wh, bq, bk, bv,
                                                                 Qh, Kh, Vh);

    attn_h<<<dim3(SEQ / 128, NH, BATCH), 256>>>(Qh, Kh, Vh, x, ch);

    gemm_o<<<dim3(ED / 128, MTOT / 128), 256, GEMM_SMEM>>>(ch, wh + 3 * (size_t)ED * ED,
                                                           bo, out);
}

// round 16
// speedup vs baseline: 1.0179x; 1.0179x over previous
#include <cuda_runtime.h>
#include <cuda_fp16.h>
#include <stdint.h>

#define ED   1024
#define NH   16
#define HD   64
#define SEQ  2048
#define BATCH 2
#define MTOT (BATCH*SEQ)

// scratch (__device__ globals: allocation-free rule)
__device__ __half g_Qh[MTOT * ED];
__device__ __half g_Kh[MTOT * ED];
__device__ __half g_Vh[MTOT * ED];
__device__ __half g_xh[MTOT * ED];
__device__ __half g_ch[MTOT * ED];
__device__ __half g_wh[4][ED * ED];        // K-major [N][K]; [0..2] packed QKV

// Q pre-scale: (1/sqrt(64)) * log2(e)  -> softmax in exp2 domain
#define QSCALE 0.1803368801111164f

// ---------------------------------------------------------------------------
// helpers
// ---------------------------------------------------------------------------
__device__ __forceinline__ uint32_t packh(__half a, __half b) {
    return (uint32_t)__half_as_ushort(a) | ((uint32_t)__half_as_ushort(b) << 16);
}
__device__ __forceinline__ void mma16(float* d, const uint32_t* a, uint32_t b0, uint32_t b1) {
    asm volatile(
        "mma.sync.aligned.m16n8k16.row.col.f32.f16.f16.f32 "
        "{%0,%1,%2,%3}, {%4,%5,%6,%7}, {%8,%9}, {%0,%1,%2,%3};\n"
        : "+f"(d[0]), "+f"(d[1]), "+f"(d[2]), "+f"(d[3])
        : "r"(a[0]), "r"(a[1]), "r"(a[2]), "r"(a[3]), "r"(b0), "r"(b1));
}
__device__ __forceinline__ void cpa16(void* sdst, const void* gsrc) {
    uint32_t sa = (uint32_t)__cvta_generic_to_shared(sdst);
    asm volatile("cp.async.cg.shared.global [%0], [%1], 16;\n" :: "r"(sa), "l"(gsrc));
}
#define CP_COMMIT() asm volatile("cp.async.commit_group;\n" ::: "memory")
#define CP_WAIT1()  asm volatile("cp.async.wait_group 1;\n" ::: "memory")
#define CP_WAIT0()  asm volatile("cp.async.wait_group 0;\n" ::: "memory")

__device__ __forceinline__ void ldmx4(uint32_t& r0, uint32_t& r1, uint32_t& r2,
                                      uint32_t& r3, uint32_t saddr) {
    asm volatile("ldmatrix.sync.aligned.m8n8.x4.shared.b16 {%0,%1,%2,%3}, [%4];"
                 : "=r"(r0), "=r"(r1), "=r"(r2), "=r"(r3) : "r"(saddr));
}
__device__ __forceinline__ void ldmx4t(uint32_t& r0, uint32_t& r1, uint32_t& r2,
                                       uint32_t& r3, uint32_t saddr) {
    asm volatile("ldmatrix.sync.aligned.m8n8.x4.trans.shared.b16 {%0,%1,%2,%3}, [%4];"
                 : "=r"(r0), "=r"(r1), "=r"(r2), "=r"(r3) : "r"(saddr));
}
__device__ __forceinline__ void ldmx2t(uint32_t& r0, uint32_t& r1, uint32_t saddr) {
    asm volatile("ldmatrix.sync.aligned.m8n8.x2.trans.shared.b16 {%0,%1}, [%2];"
                 : "=r"(r0), "=r"(r1) : "r"(saddr));
}

// ---------------------------------------------------------------------------
// prep: one launch does all fp32->fp16 rounding.
//   z in [0,3]: weight z transpose+round (only blockIdx.x < 32 active)
//   z == 4   : x rounding (flat, all 128x32 blocks active)
// block = (32, 8)
// ---------------------------------------------------------------------------
__global__ void __launch_bounds__(256)
prep(const float* __restrict__ X, const float* __restrict__ W0,
     const float* __restrict__ W1, const float* __restrict__ W2,
     const float* __restrict__ W3, __half* __restrict__ xh,
     __half* __restrict__ whBase)
{
    const int tx = threadIdx.x, ty = threadIdx.y;
    const int z = blockIdx.z;

    if (z == 4) {
        // x rounding: 4096 blocks x 256 threads x 4 floats
        int bid = blockIdx.y * 128 + blockIdx.x;
        int i = bid * 256 + ty * 32 + tx;
        float4 v = ((const float4*)X)[i];
        ((uint2*)xh)[i] = make_uint2(packh(__float2half_rn(v.x), __float2half_rn(v.y)),
                                     packh(__float2half_rn(v.z), __float2half_rn(v.w)));
        return;
    }
    if (blockIdx.x >= 32) return;

    __shared__ float t[32][33];
    const float* W = (z == 0) ? W0 : (z == 1) ? W1 : (z == 2) ? W2 : W3;
    __half* bh = whBase + (size_t)z * ED * ED;
    int k0 = blockIdx.x * 32, n0 = blockIdx.y * 32;
    #pragma unroll
    for (int i = 0; i < 4; i++)
        t[ty + 8 * i][tx] = W[(size_t)(k0 + ty + 8 * i) * ED + n0 + tx];
    __syncthreads();
    #pragma unroll
    for (int i = 0; i < 4; i++)
        bh[(size_t)(n0 + ty + 8 * i) * ED + k0 + tx] = __float2half_rn(t[tx][ty + 8 * i]);
}

// ---------------------------------------------------------------------------
// fp16 GEMM: 128x128 tile, k-chunk 64, 8 warps (2x4), warp tile 64x32.
// 2-stage cp.async buffer with ONE barrier per chunk (wait -> sync ->
// stage(c+1) -> compute(c)). Dynamic smem 72KB. ldmatrix.x4 frags. Pitch 72.
// ---------------------------------------------------------------------------
#define GP   72
#define GSTG (128 * GP)                 // halves per array (A or B) per stage
#define GST2 (2 * GSTG)                 // halves per stage (A + B)
#define NCH  16                         // k chunks of 64
#define GEMM_SMEM (2 * GST2 * 2)        // 73728 bytes

#define GEMM_MAIN(A_, B_)                                                          \
    extern __shared__ __half hsm[];                                                \
    const int tid = threadIdx.x;                                                   \
    const int w = tid >> 5, lane = tid & 31, g = lane >> 2, t = lane & 3;          \
    const int wm = w >> 2, wn = w & 3;                                             \
    const int m0 = blockIdx.y * 128;                                               \
    const int nrow0 = blockIdx.x * 128;                                            \
    const uint32_t hsmu = (uint32_t)__cvta_generic_to_shared(hsm);                 \
    const uint32_t aoff = (uint32_t)(((lane & 15) * GP + (lane >> 4) * 8) * 2);    \
    const uint32_t boff = (uint32_t)((((lane & 7) + ((lane >> 4) << 3)) * GP +     \
                                      (((lane >> 3) & 1) * 8)) * 2);               \
    float acc[4][4][4] = {};                                                       \
    auto stage = [&](int c, int s) {                                               \
        __half* base = hsm + (size_t)s * GST2;                                     \
        const int k0 = c * 64;                                                     \
        _Pragma("unroll")                                                          \
        for (int i = 0; i < 4; i++) {                                              \
            int id = i * 256 + tid;                                                \
            int r = id >> 3, c8 = (id & 7) << 3;                                   \
            cpa16(base + r * GP + c8,        A_ + (size_t)(m0 + r) * ED + k0 + c8);\
            cpa16(base + GSTG + r * GP + c8, B_ + (size_t)(nrow0 + r) * ED + k0 + c8);\
        }                                                                          \
        CP_COMMIT();                                                               \
    };                                                                             \
    stage(0, 0);                                                                   \
    for (int c = 0; c < NCH; c++) {                                                \
        CP_WAIT0();       /* chunk c landed (only pending group) */                \
        __syncthreads();  /* visible to all; compute(c-1) done -> slot free */     \
        if (c + 1 < NCH) stage(c + 1, (c + 1) & 1);                                \
        const uint32_t cAu = hsmu + (uint32_t)((c & 1) * GST2 * 2);                \
        const uint32_t cBu = cAu + (uint32_t)(GSTG * 2);                           \
        _Pragma("unroll")                                                          \
        for (int ks = 0; ks < 4; ks++) {                                           \
            uint32_t af[4][4];                                                     \
            _Pragma("unroll")                                                      \
            for (int mt = 0; mt < 4; mt++)                                         \
                ldmx4(af[mt][0], af[mt][1], af[mt][2], af[mt][3],                  \
                      cAu + (uint32_t)((((wm * 64 + mt * 16) * GP) + ks * 16) * 2) \
                          + aoff);                                                 \
            uint32_t bf[4][2];                                                     \
            _Pragma("unroll")                                                      \
            for (int np = 0; np < 2; np++)                                         \
                ldmx4(bf[2 * np][0], bf[2 * np][1], bf[2 * np + 1][0],             \
                      bf[2 * np + 1][1],                                           \
                      cBu + (uint32_t)((((wn * 32 + np * 16) * GP) + ks * 16) * 2) \
                          + boff);                                                 \
            _Pragma("unroll")                                                      \
            for (int mt = 0; mt < 4; mt++)                                         \
                _Pragma("unroll")                                                  \
                for (int nc = 0; nc < 4; nc++)                                     \
                    mma16(acc[mt][nc], af[mt], bf[nc][0], bf[nc][1]);              \
        }                                                                          \
    }

// fused QKV: B packed [3072][1024]; seg 0=Q (xQSCALE, exp2 domain), 1=K, 2=V
__global__ void __launch_bounds__(256, 2)
gemm_qkv(const __half* __restrict__ A, const __half* __restrict__ B,
         const float* __restrict__ bq, const float* __restrict__ bk,
         const float* __restrict__ bv,
         __half* __restrict__ Qh, __half* __restrict__ Kh, __half* __restrict__ Vh)
{
    GEMM_MAIN(A, B)

    const int seg = blockIdx.x >> 3;
    const int ncol0 = (blockIdx.x & 7) * 128;
    const float* bias = (seg == 0) ? bq : (seg == 1) ? bk : bv;
    __half* O = (seg == 0) ? Qh : (seg == 1) ? Kh : Vh;
    const float sc = (seg == 0) ? QSCALE : 1.0f;

    #pragma unroll
    for (int mt = 0; mt < 4; mt++) {
        int row = m0 + wm * 64 + mt * 16 + g;
        #pragma unroll
        for (int nc = 0; nc < 4; nc++) {
            int col = ncol0 + wn * 32 + nc * 8 + 2 * t;
            float b0 = bias[col], b1 = bias[col + 1];
            *(uint32_t*)(O + (size_t)row * ED + col) =
                packh(__float2half_rn((acc[mt][nc][0] + b0) * sc),
                      __float2half_rn((acc[mt][nc][1] + b1) * sc));
            *(uint32_t*)(O + (size_t)(row + 8) * ED + col) =
                packh(__float2half_rn((acc[mt][nc][2] + b0) * sc),
                      __float2half_rn((acc[mt][nc][3] + b1) * sc));
        }
    }
}

// O projection: float out
__global__ void __launch_bounds__(256, 2)
gemm_o(const __half* __restrict__ A, const __half* __restrict__ B,
       const float* __restrict__ bias, float* __restrict__ out)
{
    GEMM_MAIN(A, B)

    #pragma unroll
    for (int mt = 0; mt < 4; mt++) {
        int row = m0 + wm * 64 + mt * 16 + g;
        #pragma unroll
        for (int nc = 0; nc < 4; nc++) {
            int col = nrow0 + wn * 32 + nc * 8 + 2 * t;
            float b0 = bias[col], b1 = bias[col + 1];
            *(float2*)(out + (size_t)row * ED + col) =
                make_float2(acc[mt][nc][0] + b0, acc[mt][nc][1] + b1);
            *(float2*)(out + (size_t)(row + 8) * ED + col) =
                make_float2(acc[mt][nc][2] + b0, acc[mt][nc][3] + b1);
        }
    }
}

// ---------------------------------------------------------------------------
// fp16 flash attention (exact R11 structure), exp2 domain, 2 CTAs/SM.
// h2exp2 P; row-sum via ones-block mma (V cols 64..71, all ones).
// ---------------------------------------------------------------------------
#define PH   72
#define HSTG (64 * PH)

__global__ void __launch_bounds__(256, 2)
attn_h(const __half* __restrict__ Q, const __half* __restrict__ K,
       const __half* __restrict__ V, const float* __restrict__ X,
       __half* __restrict__ CH)
{
    __shared__ __half asm_[4 * HSTG];       // 36864 B
    __half* sK = asm_;
    __half* sV = asm_ + 2 * HSTG;

    const int tid = threadIdx.x;
    const int w = tid >> 5, lane = tid & 31, g = lane >> 2, t = lane & 3;
    const int qt = blockIdx.x, h = blockIdx.y, b = blockIdx.z;
    const int qrow0 = b * SEQ + qt * 128;
    const int coff  = h * HD;

    const int matq = lane >> 3;
    const uint32_t ldmoffV = (uint32_t)((((matq & 1) * 8 + (lane & 7)) * PH +
                                         (matq >> 1) * 8) * 2);          // V x4 trans
    const uint32_t ldmoffK = (uint32_t)((((lane & 7) + ((lane >> 4) << 3)) * PH +
                                         (((lane >> 3) & 1) * 8)) * 2);  // K x4 B-frag
    const uint32_t ldmoffL = (uint32_t)(((((lane >> 3) & 1) * 8 + (lane & 7)) * PH) * 2)
                             + 64 * 2;                                   // ones x2 trans
    const uint32_t sKu = (uint32_t)__cvta_generic_to_shared(sK);
    const uint32_t sVu = (uint32_t)__cvta_generic_to_shared(sV);

    // init V cols 64..71 in both buffers: ALL ones (row-sum via mma, lane-uniform)
    for (int i = tid; i < 2 * 64; i += 256) {
        int bf = i >> 6, r = i & 63;
        __half* dst = sV + bf * HSTG + r * PH + 64;
        #pragma unroll
        for (int j = 0; j < 8; j++) dst[j] = __float2half(1.0f);
    }

    uint32_t qf[4][4];
    {
        const int r0 = qrow0 + w * 16 + g;
        #pragma unroll
        for (int kc = 0; kc < 4; kc++) {
            int c0 = coff + kc * 16 + 2 * t;
            qf[kc][0] = *(const uint32_t*)(Q + (size_t)r0 * ED + c0);
            qf[kc][1] = *(const uint32_t*)(Q + (size_t)(r0 + 8) * ED + c0);
            qf[kc][2] = *(const uint32_t*)(Q + (size_t)r0 * ED + c0 + 8);
            qf[kc][3] = *(const uint32_t*)(Q + (size_t)(r0 + 8) * ED + c0 + 8);
        }
    }

    auto stage = [&](int kt, int s) {
        const int krow0 = b * SEQ + kt * 64;
        __half* dK = sK + s * HSTG;
        __half* dV = sV + s * HSTG;
        #pragma unroll
        for (int i = 0; i < 2; i++) {
            int id = i * 256 + tid;
            int r = id >> 3, c8 = (id & 7) << 3;
            cpa16(dK + r * PH + c8, K + (size_t)(krow0 + r) * ED + coff + c8);
            cpa16(dV + r * PH + c8, V + (size_t)(krow0 + r) * ED + coff + c8);
        }
        CP_COMMIT();
    };

    stage(0, 0);

    float m1 = -1e30f, m2 = -1e30f;
    float ol[4] = {};                        // [0]=l(row g), [2]=l(row g+8)
    float o[8][4] = {};

    int buf = 0;
    for (int kt = 0; kt < SEQ / 64; kt++) {
        if (kt + 1 < SEQ / 64) { stage(kt + 1, buf ^ 1); CP_WAIT1(); }
        else                   { CP_WAIT0(); }
        __syncthreads();

        const uint32_t cKu = sKu + (uint32_t)(buf * HSTG * 2);
        const uint32_t cVu = sVu + (uint32_t)(buf * HSTG * 2);

        // S = Q @ K^T
        float s[8][4] = {};
        #pragma unroll
        for (int kc = 0; kc < 4; kc++) {
            #pragma unroll
            for (int np = 0; np < 4; np++) {
                uint32_t b00, b01, b10, b11;
                ldmx4(b00, b01, b10, b11,
                      cKu + (uint32_t)((np * 16 * PH + kc * 16) * 2) + ldmoffK);
                mma16(s[2 * np],     qf[kc], b00, b01);
                mma16(s[2 * np + 1], qf[kc], b10, b11);
            }
        }

        // online softmax in exp2 domain (rows g, g+8; quad reduce for max)
        float tm1 = -1e30f, tm2 = -1e30f;
        #pragma unroll
        for (int nc = 0; nc < 8; nc++) {
            tm1 = fmaxf(tm1, fmaxf(s[nc][0], s[nc][1]));
            tm2 = fmaxf(tm2, fmaxf(s[nc][2], s[nc][3]));
        }
        tm1 = fmaxf(tm1, __shfl_xor_sync(0xffffffffu, tm1, 1));
        tm1 = fmaxf(tm1, __shfl_xor_sync(0xffffffffu, tm1, 2));
        tm2 = fmaxf(tm2, __shfl_xor_sync(0xffffffffu, tm2, 1));
        tm2 = fmaxf(tm2, __shfl_xor_sync(0xffffffffu, tm2, 2));

        float mn1 = fmaxf(m1, tm1), mn2 = fmaxf(m2, tm2);
        float c1 = exp2f(m1 - mn1), c2 = exp2f(m2 - mn2);
        m1 = mn1; m2 = mn2;

        // P in fp16 via packed MUFU exp2
        uint32_t p0[8], p1[8];
        #pragma unroll
        for (int nc = 0; nc < 8; nc++) {
            __half2 e01 = h2exp2(__floats2half2_rn(s[nc][0] - mn1, s[nc][1] - mn1));
            __half2 e23 = h2exp2(__floats2half2_rn(s[nc][2] - mn2, s[nc][3] - mn2));
            p0[nc] = *(uint32_t*)&e01;
            p1[nc] = *(uint32_t*)&e23;
        }

        // rescale running O and l
        ol[0] *= c1; ol[2] *= c2;
        #pragma unroll
        for (int nc = 0; nc < 8; nc++) {
            o[nc][0] *= c1; o[nc][1] *= c1;
            o[nc][2] *= c2; o[nc][3] *= c2;
        }

        // O += P @ V ; l += P @ ones (V ones-block)
        #pragma unroll
        for (int kc = 0; kc < 4; kc++) {
            uint32_t a[4] = { p0[2 * kc], p1[2 * kc], p0[2 * kc + 1], p1[2 * kc + 1] };
            uint32_t lb0, lb1;
            ldmx2t(lb0, lb1, cVu + (uint32_t)((kc * 16 * PH) * 2) + ldmoffL);
            mma16(ol, a, lb0, lb1);
            #pragma unroll
            for (int np = 0; np < 4; np++) {
                uint32_t r0, r1, r2, r3;
                ldmx4t(r0, r1, r2, r3,
                       cVu + (uint32_t)((kc * 16 * PH + np * 16) * 2) + ldmoffV);
                mma16(o[2 * np],     a, r0, r1);
                mma16(o[2 * np + 1], a, r2, r3);
            }
        }

        __syncthreads();
        buf ^= 1;
    }

    const float i1 = 1.f / ol[0], i2 = 1.f / ol[2];
    const int r0 = qrow0 + w * 16 + g;
    #pragma unroll
    for (int nc = 0; nc < 8; nc++) {
        int col = coff + nc * 8 + 2 * t;
        float2 x0 = *(const float2*)(X + (size_t)r0 * ED + col);
        float2 x1 = *(const float2*)(X + (size_t)(r0 + 8) * ED + col);
        *(uint32_t*)(CH + (size_t)r0 * ED + col) =
            packh(__float2half_rn(o[nc][0] * i1 + x0.x),
                  __float2half_rn(o[nc][1] * i1 + x0.y));
        *(uint32_t*)(CH + (size_t)(r0 + 8) * ED + col) =
            packh(__float2half_rn(o[nc][2] * i2 + x1.x),
                  __float2half_rn(o[nc][3] * i2 + x1.y));
    }
}

// ---------------------------------------------------------------------------
extern "C" void kernel_launch(void* const* d_in, const int* in_sizes, int n_in,
                              void* d_out, int out_size)
{
    const float* x  = (const float*)d_in[0];
    const float* wq = (const float*)d_in[1];
    const float* bq = (const float*)d_in[2];
    const float* wk = (const float*)d_in[3];
    const float* bk = (const float*)d_in[4];
    const float* wv = (const float*)d_in[5];
    const float* bv = (const float*)d_in[6];
    const float* wo = (const float*)d_in[7];
    const float* bo = (const float*)d_in[8];
    float* out = (float*)d_out;

    __half *Qh, *Kh, *Vh, *xh, *ch, *wh;
    cudaGetSymbolAddress((void**)&Qh, g_Qh);
    cudaGetSymbolAddress((void**)&Kh, g_Kh);
    cudaGetSymbolAddress((void**)&Vh, g_Vh);
    cudaGetSymbolAddress((void**)&xh, g_xh);
    cudaGetSymbolAddress((void**)&ch, g_ch);
    cudaGetSymbolAddress((void**)&wh, g_wh);

    cudaFuncSetAttribute(gemm_qkv, cudaFuncAttributeMaxDynamicSharedMemorySize, GEMM_SMEM);
    cudaFuncSetAttribute(gemm_o,   cudaFuncAttributeMaxDynamicSharedMemorySize, GEMM_SMEM);

    // all rounding in ONE launch
    prep<<<dim3(128, 32, 5), dim3(32, 8)>>>(x, wq, wk, wv, wo, xh, wh);

    gemm_qkv<<<dim3(3 * ED / 128, MTOT / 128), 256, GEMM_SMEM>>>(xh, wh, bq, bk, bv,
                                                                 Qh, Kh, Vh);

    attn_h<<<dim3(SEQ / 128, NH, BATCH), 256>>>(Qh, Kh, Vh, x, ch);

    gemm_o<<<dim3(ED / 128, MTOT / 128), 256, GEMM_SMEM>>>(ch, wh + 3 * (size_t)ED * ED,
                                                           bo, out);
}